// round 6
// baseline (speedup 1.0000x reference)
#include <cuda_runtime.h>
#include <cuda_fp16.h>
#include <mma.h>
#include <cstdint>
#include <cstddef>
using namespace nvcuda;

#define NNODES 55296
#define NEDGES 221184
#define N32 (NNODES * 32)

// ------------------------- device scratch -----------------------------------
__device__ __align__(256) float g_h[2 * N32];
__device__ __align__(256) float g_agg[2 * N32];
__device__ __align__(256) __half g_tA[(size_t)NEDGES * 96];  // A' = [hi|lo|hi]
__device__ __align__(256) __half g_Bt[96 * 1024];            // B' rows: hi,hi,lo
__device__ __align__(256) float g_biasp[1024];               // eb2 permuted
__device__ __align__(256) __half g_We[(size_t)NEDGES * 1024]; // [e][q][o][8h]

__device__ __forceinline__ float fsig(float x) { return 1.f / (1.f + __expf(-x)); }

// ------------------------- k0: zero accumulator (once) -----------------------
__global__ void zero_kernel() {
    int i = blockIdx.x * 256 + threadIdx.x;
    if (i < 2 * N32) g_agg[i] = 0.f;
}

// ------------ k1: build B' [96][1024] fp16 (+ permuted bias) -----------------
// col j = q*256 + o*8 + hl ; h = q*8+hl ; o = (j>>3)&31. rows: 0-31 hi, 32-63 hi, 64-95 lo
__global__ void reorder_kernel(const float* __restrict__ ew2,
                               const float* __restrict__ eb2) {
    int i = blockIdx.x * 256 + threadIdx.x;
    if (i >= 96 * 1024) return;
    int kp = i >> 10, j = i & 1023;
    int h = ((j >> 8) << 3) + (j & 7), o = (j >> 3) & 31;
    int k = (kp < 32) ? kp : (kp < 64 ? kp - 32 : kp - 64);
    float w = ew2[k * 1024 + h * 32 + o];
    __half hi = __float2half(w);
    g_Bt[i] = (kp < 64) ? hi : __float2half(w - __half2float(hi));
    if (i < 1024) g_biasp[i] = eb2[h * 32 + o];
}

// ------------ k2: t = relu(rel@ew1+eb1) -> A' fp16 [e][hi|lo|hi] -------------
__global__ void t_kernel(const float4* __restrict__ rel4,
                         const float* __restrict__ ew1,
                         const float* __restrict__ eb1) {
    int g = blockIdx.x * 256 + threadIdx.x;
    int e = g >> 5, k = g & 31;
    if (e >= NEDGES) return;
    float4 r = rel4[e];
    float v = eb1[k] + r.x * ew1[k] + r.y * ew1[32 + k] + r.z * ew1[64 + k] +
              r.w * ew1[96 + k];
    v = fmaxf(v, 0.f);
    __half hi = __float2half(v);
    __half lo = __float2half(v - __half2float(hi));
    size_t b = (size_t)e * 96 + k;
    g_tA[b] = hi;
    g_tA[b + 32] = lo;
    g_tA[b + 64] = hi;
}

// ------------------------- k3: h0 projection (warp per node) -----------------
__global__ __launch_bounds__(256) void h0_kernel(const float* __restrict__ x,
                                                 const float* __restrict__ pw1,
                                                 const float* __restrict__ pb1,
                                                 const float* __restrict__ pw2,
                                                 const float* __restrict__ pb2) {
    __shared__ float sW1[1024], sW2[1024];
    int tid = threadIdx.x, lane = tid & 31;
    for (int i = tid; i < 1024; i += 256) { sW1[i] = pw1[i]; sW2[i] = pw2[i]; }
    __syncthreads();
    int gw = blockIdx.x * 8 + (tid >> 5);
    float xr = x[(size_t)gw * 32 + lane];
    float t1 = pb1[lane];
#pragma unroll
    for (int h = 0; h < 32; h++)
        t1 = fmaf(__shfl_sync(0xffffffffu, xr, h), sW1[h * 32 + lane], t1);
    t1 = fmaxf(t1, 0.f);
    float o = pb2[lane];
#pragma unroll
    for (int h = 0; h < 32; h++)
        o = fmaf(__shfl_sync(0xffffffffu, t1, h), sW2[h * 32 + lane], o);
    g_h[(size_t)gw * 32 + lane] = o;
}

// ------------------------- k4: We GEMM via wmma (HMMA) -----------------------
// [128 edges x 96] @ [96 x 1024], fp32 accum, +bias, fp16 out in blocked layout
#define WSM_A 0          // 128*96 half  = 24576
#define WSM_B 24576      // 96*64 half   = 12288
#define WSM_C 36864      // 8*16*68 f32  = 34816
#define WSM_BIAS 71680   // 64 f32       = 256
#define WSM_TOT 71936

__global__ __launch_bounds__(256) void we_wmma_kernel() {
    extern __shared__ char sm[];
    __half* sA = (__half*)(sm + WSM_A);
    __half* sB = (__half*)(sm + WSM_B);
    float* sC = (float*)(sm + WSM_C);
    float* sBias = (float*)(sm + WSM_BIAS);
    int tid = threadIdx.x, wid = tid >> 5, lane = tid & 31;

    const uint4* ga = (const uint4*)(g_tA + (size_t)blockIdx.x * 128 * 96);
    uint4* sa4 = (uint4*)sA;
#pragma unroll
    for (int r = 0; r < 6; r++) sa4[tid + r * 256] = ga[tid + r * 256];

    float* sCw = sC + wid * 16 * 68;
    for (int nt = 0; nt < 16; nt++) {
        __syncthreads();
#pragma unroll
        for (int r = 0; r < 3; r++) {
            int i = tid + r * 256;            // 0..767 (96 rows x 8 x 16B)
            int k = i >> 3, seg = i & 7;
            ((uint4*)sB)[i] = *(const uint4*)(g_Bt + k * 1024 + nt * 64 + seg * 8);
        }
        if (tid < 64) sBias[tid] = g_biasp[nt * 64 + tid];
        __syncthreads();

        wmma::fragment<wmma::accumulator, 16, 16, 16, float> acc[4];
#pragma unroll
        for (int f = 0; f < 4; f++) wmma::fill_fragment(acc[f], 0.f);
#pragma unroll
        for (int k = 0; k < 6; k++) {
            wmma::fragment<wmma::matrix_a, 16, 16, 16, __half, wmma::row_major> af;
            wmma::load_matrix_sync(af, sA + wid * 16 * 96 + k * 16, 96);
#pragma unroll
            for (int f = 0; f < 4; f++) {
                wmma::fragment<wmma::matrix_b, 16, 16, 16, __half, wmma::row_major> bf;
                wmma::load_matrix_sync(bf, sB + k * 16 * 64 + f * 16, 64);
                wmma::mma_sync(acc[f], af, bf, acc[f]);
            }
        }
#pragma unroll
        for (int f = 0; f < 4; f++)
            wmma::store_matrix_sync(sCw + f * 16, acc[f], 68, wmma::mem_row_major);
        __syncwarp();

        int r = lane & 15, cb = lane >> 4;
        const float* rowp = sCw + r * 68 + cb * 32;
        const float* bp = sBias + cb * 32;
        uint32_t p[16];
#pragma unroll
        for (int i = 0; i < 16; i++) {
            __half2 hh = __floats2half2_rn(rowp[2 * i] + bp[2 * i],
                                           rowp[2 * i + 1] + bp[2 * i + 1]);
            p[i] = *(uint32_t*)&hh;
        }
        int e = blockIdx.x * 128 + wid * 16 + r;
        uint4* dst = (uint4*)(void*)g_We + (size_t)e * 128 + nt * 8 + cb * 4;
        dst[0] = make_uint4(p[0], p[1], p[2], p[3]);
        dst[1] = make_uint4(p[4], p[5], p[6], p[7]);
        dst[2] = make_uint4(p[8], p[9], p[10], p[11]);
        dst[3] = make_uint4(p[12], p[13], p[14], p[15]);
    }
}

// ------------------------- k5: msg + scatter (warp per edge, lane = o) -------
__global__ __launch_bounds__(256) void msg_kernel(const int* __restrict__ src,
                                                  const int* __restrict__ dst) {
    __shared__ __align__(16) float ns[8][2][32];
    const int w = threadIdx.x >> 5, lane = threadIdx.x & 31;
    const int e = blockIdx.x * 8 + w;
    int s = __ldg(&src[e]);
    int d = __ldg(&dst[e]);
    ns[w][0][lane] = g_h[(size_t)s * 32 + lane];
    ns[w][1][lane] = g_h[N32 + (size_t)s * 32 + lane];
    __syncwarp();
    const uint4* wp = (const uint4*)(const void*)g_We + (size_t)e * 128;
    float a0 = 0.f, a1 = 0.f;
#pragma unroll
    for (int q = 0; q < 4; q++) {
        uint4 qv = wp[q * 32 + lane];
        uint32_t w4[4] = {qv.x, qv.y, qv.z, qv.w};
#pragma unroll
        for (int u = 0; u < 4; u++) {
            float2 wf = __half22float2(*(__half2*)&w4[u]);
            int h = q * 8 + 2 * u;
            float2 p0 = *(const float2*)&ns[w][0][h];
            float2 p1 = *(const float2*)&ns[w][1][h];
            a0 += p0.x * wf.x + p0.y * wf.y;
            a1 += p1.x * wf.x + p1.y * wf.y;
        }
    }
    float u = __shfl_down_sync(0xffffffffu, a0, 1);
    float v = __shfl_up_sync(0xffffffffu, a1, 1);
    if (!(lane & 1))
        asm volatile("red.global.add.v2.f32 [%0], {%1,%2};"
                     :: "l"(&g_agg[(size_t)d * 32 + lane]), "f"(a0), "f"(u) : "memory");
    else
        asm volatile("red.global.add.v2.f32 [%0], {%1,%2};"
                     :: "l"(&g_agg[N32 + (size_t)d * 32 + lane - 1]), "f"(v), "f"(a1)
                     : "memory");
}

// ------------------------- k6: relu + GRU (warp per node), resets agg --------
__global__ __launch_bounds__(256) void gru_kernel(const float* __restrict__ convb,
                                                  const float* __restrict__ wih,
                                                  const float* __restrict__ whh,
                                                  const float* __restrict__ bih,
                                                  const float* __restrict__ bhh,
                                                  float* __restrict__ outp) {
    __shared__ float sWih[3072], sWhh[3072];
    int tid = threadIdx.x, lane = tid & 31;
    for (int i = tid; i < 3072; i += 256) {
        int j = i >> 5, h = i & 31;
        sWih[h * 96 + j] = wih[i];
        sWhh[h * 96 + j] = whh[i];
    }
    __syncthreads();
    int gw = blockIdx.x * 8 + (tid >> 5);
    size_t idx = (size_t)gw * 32 + lane;
    float node = fmaxf(g_agg[idx] + convb[lane], 0.f);
    g_agg[idx] = 0.f;
    float hid = g_h[idx];
    float gx0 = bih[lane], gx1 = bih[32 + lane], gx2 = bih[64 + lane];
    float gh0 = bhh[lane], gh1 = bhh[32 + lane], gh2 = bhh[64 + lane];
#pragma unroll
    for (int h = 0; h < 32; h++) {
        float nv = __shfl_sync(0xffffffffu, node, h);
        float hv = __shfl_sync(0xffffffffu, hid, h);
        const float* wi = &sWih[h * 96];
        const float* wh = &sWhh[h * 96];
        gx0 = fmaf(nv, wi[lane], gx0);
        gx1 = fmaf(nv, wi[32 + lane], gx1);
        gx2 = fmaf(nv, wi[64 + lane], gx2);
        gh0 = fmaf(hv, wh[lane], gh0);
        gh1 = fmaf(hv, wh[32 + lane], gh1);
        gh2 = fmaf(hv, wh[64 + lane], gh2);
    }
    float r = fsig(gx0 + gh0);
    float z = fsig(gx1 + gh1);
    float n = tanhf(gx2 + r * gh2);
    float hn = (1.f - z) * n + z * hid;
    g_h[idx] = hn;
    if (outp) outp[idx] = hn;
}

// ------------------------- launch -------------------------------------------
extern "C" void kernel_launch(void* const* d_in, const int* in_sizes, int n_in,
                              void* d_out, int out_size) {
    const float* x     = (const float*)d_in[0];
    const float* rel   = (const float*)d_in[1];
    const float* pw1   = (const float*)d_in[2];
    const float* pb1   = (const float*)d_in[3];
    const float* pw2   = (const float*)d_in[4];
    const float* pb2   = (const float*)d_in[5];
    const float* ew1   = (const float*)d_in[6];
    const float* eb1   = (const float*)d_in[7];
    const float* ew2   = (const float*)d_in[8];
    const float* eb2   = (const float*)d_in[9];
    const float* convb = (const float*)d_in[10];
    const float* wih   = (const float*)d_in[11];
    const float* whh   = (const float*)d_in[12];
    const float* bih   = (const float*)d_in[13];
    const float* bhh   = (const float*)d_in[14];
    const int*   src   = (const int*)d_in[15];
    const int*   dst   = (const int*)d_in[16];
    float* out = (float*)d_out;

    reorder_kernel<<<384, 256>>>(ew2, eb2);
    t_kernel<<<(NEDGES * 32) / 256, 256>>>((const float4*)rel, ew1, eb1);
    h0_kernel<<<(2 * NNODES) / 8, 256>>>(x, pw1, pb1, pw2, pb2);
    zero_kernel<<<(2 * N32) / 256, 256>>>();
    cudaFuncSetAttribute(we_wmma_kernel,
                         cudaFuncAttributeMaxDynamicSharedMemorySize, WSM_TOT);
    we_wmma_kernel<<<NEDGES / 128, 256, WSM_TOT>>>();
    for (int step = 0; step < 3; step++) {
        msg_kernel<<<NEDGES / 8, 256>>>(src, dst);
        gru_kernel<<<(2 * NNODES) / 8, 256>>>(convb, wih, whh, bih, bhh,
                                              step == 2 ? out : nullptr);
    }
}

// round 7
// speedup vs baseline: 1.4112x; 1.4112x over previous
#include <cuda_runtime.h>
#include <cuda_fp16.h>
#include <mma.h>
#include <cstdint>
#include <cstddef>
using namespace nvcuda;

#define NNODES 55296
#define NEDGES 221184
#define N32 (NNODES * 32)

// ------------------------- device scratch -----------------------------------
__device__ __align__(256) float g_h[2 * N32];
__device__ __align__(256) float g_agg[2 * N32];
__device__ __align__(256) __half g_tA[(size_t)NEDGES * 64];   // A' = [hi32|lo32]
__device__ __align__(256) __half g_Bt[64 * 1024];             // B' hi rows x2
__device__ __align__(256) float g_biasp[1024];                // eb2 permuted
__device__ __align__(256) __half g_We[(size_t)NEDGES * 1024]; // [e][j] j=(q,o,hl)

__device__ __forceinline__ float fsig(float x) { return 1.f / (1.f + __expf(-x)); }
__device__ __forceinline__ uint64_t mkpol_ef() {
    uint64_t p;
    asm("createpolicy.fractional.L2::evict_first.b64 %0;" : "=l"(p));
    return p;
}
__device__ __forceinline__ uint4 ld_ef(const void* gp, uint64_t pol) {
    uint4 v;
    asm volatile("ld.global.nc.L2::cache_hint.v4.u32 {%0,%1,%2,%3}, [%4], %5;"
                 : "=r"(v.x), "=r"(v.y), "=r"(v.z), "=r"(v.w)
                 : "l"(gp), "l"(pol));
    return v;
}
__device__ __forceinline__ void st_ef(void* gp, uint4 v, uint64_t pol) {
    asm volatile("st.global.L2::cache_hint.v4.b32 [%0], {%1,%2,%3,%4}, %5;"
                 :: "l"(gp), "r"(v.x), "r"(v.y), "r"(v.z), "r"(v.w), "l"(pol)
                 : "memory");
}

// ---- k0 (launch 0): fused preprocessing: B' build, bias permute, t build ----
__global__ void pre_kernel(const float* __restrict__ ew2,
                           const float* __restrict__ eb2,
                           const float4* __restrict__ rel4,
                           const float* __restrict__ ew1,
                           const float* __restrict__ eb1) {
    int b = blockIdx.x, tid = threadIdx.x;
    if (b < 256) {                       // B' [64][1024]: j = q*256+o*8+hl
        int i = b * 256 + tid;
        int kp = i >> 10, j = i & 1023;
        int h = ((j >> 8) << 3) + (j & 7), o = (j >> 3) & 31;
        g_Bt[i] = __float2half(ew2[(kp & 31) * 1024 + h * 32 + o]);
    } else if (b == 256) {               // permuted bias
#pragma unroll
        for (int u = 0; u < 4; u++) {
            int j = tid * 4 + u;
            int h = ((j >> 8) << 3) + (j & 7), o = (j >> 3) & 31;
            g_biasp[j] = eb2[h * 32 + o];
        }
    } else {                             // t = relu(rel@ew1+eb1) -> fp16 hi|lo
        int g = (b - 257) * 256 + tid;
        int e = g >> 5, k = g & 31;
        float4 r = rel4[e];
        float v = eb1[k] + r.x * ew1[k] + r.y * ew1[32 + k] + r.z * ew1[64 + k] +
                  r.w * ew1[96 + k];
        v = fmaxf(v, 0.f);
        __half hi = __float2half(v);
        g_tA[(size_t)e * 64 + k] = hi;
        g_tA[(size_t)e * 64 + 32 + k] = __float2half(v - __half2float(hi));
    }
}

// ---- k1 (launch 1): h0 projection + zero g_agg ------------------------------
__global__ __launch_bounds__(256) void h0z_kernel(const float* __restrict__ x,
                                                  const float* __restrict__ pw1,
                                                  const float* __restrict__ pb1,
                                                  const float* __restrict__ pw2,
                                                  const float* __restrict__ pb2) {
    __shared__ float sW1[1024], sW2[1024];
    int tid = threadIdx.x, lane = tid & 31;
    g_agg[blockIdx.x * 256 + tid] = 0.f;
    for (int i = tid; i < 1024; i += 256) { sW1[i] = pw1[i]; sW2[i] = pw2[i]; }
    __syncthreads();
    int gw = blockIdx.x * 8 + (tid >> 5);
    float xr = x[(size_t)gw * 32 + lane];
    float t1 = pb1[lane];
#pragma unroll
    for (int h = 0; h < 32; h++)
        t1 = fmaf(__shfl_sync(0xffffffffu, xr, h), sW1[h * 32 + lane], t1);
    t1 = fmaxf(t1, 0.f);
    float o = pb2[lane];
#pragma unroll
    for (int h = 0; h < 32; h++)
        o = fmaf(__shfl_sync(0xffffffffu, t1, h), sW2[h * 32 + lane], o);
    g_h[(size_t)gw * 32 + lane] = o;
}

// ---- k2 (launch 2): We GEMM [128x64]@[64x1024] via wmma, coalesced stores ---
#define SA 0                 // 128*72*2  = 18432
#define SB 18432             // 64*1032*2 = 132096
#define SC 150528            // 8*16*68*4 = 34816
#define SBIAS 185344         // 4096
#define STOT 189440

__global__ __launch_bounds__(256) void we_wmma_kernel() {
    extern __shared__ char sm[];
    __half* sA = (__half*)(sm + SA);
    __half* sB = (__half*)(sm + SB);
    float* sC = (float*)(sm + SC);
    float* sBias = (float*)(sm + SBIAS);
    int tid = threadIdx.x, wid = tid >> 5, lane = tid & 31;
    uint64_t pol = mkpol_ef();

    // A tile: 128 edges x 64 halves, pad to stride 72
    const uint4* ga = (const uint4*)(g_tA + (size_t)blockIdx.x * 128 * 64);
#pragma unroll
    for (int r = 0; r < 4; r++) {
        int i = tid + r * 256, row = i >> 3, c = i & 7;
        *(uint4*)(sA + row * 72 + c * 8) = ga[i];
    }
    // B' full: 64 x 1024 halves, pad to stride 1032
    const uint4* gb = (const uint4*)(const void*)g_Bt;
#pragma unroll
    for (int r = 0; r < 32; r++) {
        int i = tid + r * 256, row = i >> 7, c = i & 127;
        *(uint4*)(sB + row * 1032 + c * 8) = gb[i];
    }
#pragma unroll
    for (int r = 0; r < 4; r++) sBias[tid + r * 256] = g_biasp[tid + r * 256];
    __syncthreads();

    float* sCw = sC + wid * 16 * 68;
    const int rsub = lane >> 3, ch = lane & 7;
    for (int nt = 0; nt < 16; nt++) {
        wmma::fragment<wmma::accumulator, 16, 16, 16, float> acc[4];
#pragma unroll
        for (int f = 0; f < 4; f++) wmma::fill_fragment(acc[f], 0.f);
#pragma unroll
        for (int k = 0; k < 4; k++) {
            wmma::fragment<wmma::matrix_a, 16, 16, 16, __half, wmma::row_major> af;
            wmma::load_matrix_sync(af, sA + (wid * 16) * 72 + k * 16, 72);
#pragma unroll
            for (int f = 0; f < 4; f++) {
                wmma::fragment<wmma::matrix_b, 16, 16, 16, __half, wmma::row_major> bf;
                wmma::load_matrix_sync(bf, sB + (k * 16) * 1032 + nt * 64 + f * 16,
                                       1032);
                wmma::mma_sync(acc[f], af, bf, acc[f]);
            }
        }
        __syncwarp();
#pragma unroll
        for (int f = 0; f < 4; f++)
            wmma::store_matrix_sync(sCw + f * 16, acc[f], 68, wmma::mem_row_major);
        __syncwarp();
        // coalesced store: 8 lanes cover one edge's 128B for this nt-block
        const float* bp = sBias + nt * 64 + ch * 8;
#pragma unroll
        for (int p = 0; p < 4; p++) {
            int row = p * 4 + rsub;
            const float* rp = sCw + row * 68 + ch * 8;
            float4 v0 = *(const float4*)rp;
            float4 v1 = *(const float4*)(rp + 4);
            __half2 a = __floats2half2_rn(v0.x + bp[0], v0.y + bp[1]);
            __half2 b2 = __floats2half2_rn(v0.z + bp[2], v0.w + bp[3]);
            __half2 c2 = __floats2half2_rn(v1.x + bp[4], v1.y + bp[5]);
            __half2 d2 = __floats2half2_rn(v1.z + bp[6], v1.w + bp[7]);
            int e = blockIdx.x * 128 + wid * 16 + row;
            uint4 pk = make_uint4(*(uint32_t*)&a, *(uint32_t*)&b2,
                                  *(uint32_t*)&c2, *(uint32_t*)&d2);
            st_ef((char*)(void*)g_We + (size_t)e * 2048 + nt * 128 + ch * 16, pk,
                  pol);
        }
        __syncwarp();
    }
}

// ---- k3 (launch 3, PROFILED): msg + scatter, 2 edges per warp ---------------
__global__ __launch_bounds__(256) void msg_kernel(const int* __restrict__ src,
                                                  const int* __restrict__ dst) {
    __shared__ __align__(16) float ns[8][4][32];
    const int w = threadIdx.x >> 5, lane = threadIdx.x & 31;
    const int e0 = blockIdx.x * 16 + w * 2;
    uint64_t pol = mkpol_ef();
    int s0 = __ldg(&src[e0]), s1 = __ldg(&src[e0 + 1]);
    int d0 = __ldg(&dst[e0]), d1 = __ldg(&dst[e0 + 1]);
    ns[w][0][lane] = g_h[(size_t)s0 * 32 + lane];
    ns[w][1][lane] = g_h[N32 + (size_t)s0 * 32 + lane];
    ns[w][2][lane] = g_h[(size_t)s1 * 32 + lane];
    ns[w][3][lane] = g_h[N32 + (size_t)s1 * 32 + lane];
    uint4 q[8];
#pragma unroll
    for (int ee = 0; ee < 2; ee++)
#pragma unroll
        for (int qi = 0; qi < 4; qi++)
            q[ee * 4 + qi] = ld_ef((const char*)(const void*)g_We +
                                       (size_t)(e0 + ee) * 2048 + qi * 512 +
                                       lane * 16,
                                   pol);
    __syncwarp();
    float acc[4] = {0.f, 0.f, 0.f, 0.f};
#pragma unroll
    for (int ee = 0; ee < 2; ee++) {
#pragma unroll
        for (int qi = 0; qi < 4; qi++) {
            uint32_t w4[4] = {q[ee * 4 + qi].x, q[ee * 4 + qi].y,
                              q[ee * 4 + qi].z, q[ee * 4 + qi].w};
#pragma unroll
            for (int u = 0; u < 4; u++) {
                float2 wf = __half22float2(*(__half2*)&w4[u]);
                int h = qi * 8 + 2 * u;
                float2 p0 = *(const float2*)&ns[w][ee * 2][h];
                float2 p1 = *(const float2*)&ns[w][ee * 2 + 1][h];
                acc[ee * 2] += p0.x * wf.x + p0.y * wf.y;
                acc[ee * 2 + 1] += p1.x * wf.x + p1.y * wf.y;
            }
        }
    }
#pragma unroll
    for (int ee = 0; ee < 2; ee++) {
        int d = ee ? d1 : d0;
        float a0 = acc[ee * 2], a1 = acc[ee * 2 + 1];
        float u = __shfl_down_sync(0xffffffffu, a0, 1);
        float v = __shfl_up_sync(0xffffffffu, a1, 1);
        if (!(lane & 1))
            asm volatile("red.global.add.v2.f32 [%0], {%1,%2};"
                         :: "l"(&g_agg[(size_t)d * 32 + lane]), "f"(a0), "f"(u)
                         : "memory");
        else
            asm volatile("red.global.add.v2.f32 [%0], {%1,%2};"
                         :: "l"(&g_agg[N32 + (size_t)d * 32 + lane - 1]), "f"(v),
                            "f"(a1)
                         : "memory");
    }
}

// ---- k4: relu + GRU (warp per node), resets agg -----------------------------
__global__ __launch_bounds__(256) void gru_kernel(const float* __restrict__ convb,
                                                  const float* __restrict__ wih,
                                                  const float* __restrict__ whh,
                                                  const float* __restrict__ bih,
                                                  const float* __restrict__ bhh,
                                                  float* __restrict__ outp) {
    __shared__ float sWih[3072], sWhh[3072];
    int tid = threadIdx.x, lane = tid & 31;
    for (int i = tid; i < 3072; i += 256) {
        int j = i >> 5, h = i & 31;
        sWih[h * 96 + j] = wih[i];
        sWhh[h * 96 + j] = whh[i];
    }
    __syncthreads();
    int gw = blockIdx.x * 8 + (tid >> 5);
    size_t idx = (size_t)gw * 32 + lane;
    float node = fmaxf(g_agg[idx] + convb[lane], 0.f);
    g_agg[idx] = 0.f;
    float hid = g_h[idx];
    float gx0 = bih[lane], gx1 = bih[32 + lane], gx2 = bih[64 + lane];
    float gh0 = bhh[lane], gh1 = bhh[32 + lane], gh2 = bhh[64 + lane];
#pragma unroll
    for (int h = 0; h < 32; h++) {
        float nv = __shfl_sync(0xffffffffu, node, h);
        float hv = __shfl_sync(0xffffffffu, hid, h);
        const float* wi = &sWih[h * 96];
        const float* wh = &sWhh[h * 96];
        gx0 = fmaf(nv, wi[lane], gx0);
        gx1 = fmaf(nv, wi[32 + lane], gx1);
        gx2 = fmaf(nv, wi[64 + lane], gx2);
        gh0 = fmaf(hv, wh[lane], gh0);
        gh1 = fmaf(hv, wh[32 + lane], gh1);
        gh2 = fmaf(hv, wh[64 + lane], gh2);
    }
    float r = fsig(gx0 + gh0);
    float z = fsig(gx1 + gh1);
    float n = tanhf(gx2 + r * gh2);
    float hn = (1.f - z) * n + z * hid;
    g_h[idx] = hn;
    if (outp) outp[idx] = hn;
}

// ------------------------- launch -------------------------------------------
extern "C" void kernel_launch(void* const* d_in, const int* in_sizes, int n_in,
                              void* d_out, int out_size) {
    const float* x     = (const float*)d_in[0];
    const float* rel   = (const float*)d_in[1];
    const float* pw1   = (const float*)d_in[2];
    const float* pb1   = (const float*)d_in[3];
    const float* pw2   = (const float*)d_in[4];
    const float* pb2   = (const float*)d_in[5];
    const float* ew1   = (const float*)d_in[6];
    const float* eb1   = (const float*)d_in[7];
    const float* ew2   = (const float*)d_in[8];
    const float* eb2   = (const float*)d_in[9];
    const float* convb = (const float*)d_in[10];
    const float* wih   = (const float*)d_in[11];
    const float* whh   = (const float*)d_in[12];
    const float* bih   = (const float*)d_in[13];
    const float* bhh   = (const float*)d_in[14];
    const int*   src   = (const int*)d_in[15];
    const int*   dst   = (const int*)d_in[16];
    float* out = (float*)d_out;

    cudaFuncSetAttribute(we_wmma_kernel,
                         cudaFuncAttributeMaxDynamicSharedMemorySize, STOT);
    pre_kernel<<<257 + (NEDGES * 32) / 256, 256>>>(ew2, eb2, (const float4*)rel,
                                                   ew1, eb1);
    h0z_kernel<<<(2 * NNODES) / 8, 256>>>(x, pw1, pb1, pw2, pb2);
    we_wmma_kernel<<<NEDGES / 128, 256, STOT>>>();
    for (int step = 0; step < 3; step++) {
        msg_kernel<<<NEDGES / 16, 256>>>(src, dst);
        gru_kernel<<<(2 * NNODES) / 8, 256>>>(convb, wih, whh, bih, bhh,
                                              step == 2 ? out : nullptr);
    }
}

// round 8
// speedup vs baseline: 2.7465x; 1.9462x over previous
#include <cuda_runtime.h>
#include <cuda_fp16.h>
#include <mma.h>
#include <cstdint>
#include <cstddef>
using namespace nvcuda;

#define NNODES 55296
#define NEDGES 221184
#define N32 (NNODES * 32)

// ------------------------- device scratch -----------------------------------
__device__ __align__(256) float g_h[2 * N32];
__device__ __align__(256) float g_agg[2 * N32];
__device__ __align__(256) __half g_tA[(size_t)NEDGES * 32];   // t hi fp16
__device__ __align__(256) __half g_Bt[32 * 1024];             // B' permuted
__device__ __align__(256) float g_biasp[1024];                // eb2 permuted
__device__ __align__(256) __half g_We[(size_t)NEDGES * 1024]; // [e][j] j=(q,o,hl)

__device__ __forceinline__ float fsig(float x) { return 1.f / (1.f + __expf(-x)); }
__device__ __forceinline__ uint64_t mkpol_ef() {
    uint64_t p;
    asm("createpolicy.fractional.L2::evict_first.b64 %0;" : "=l"(p));
    return p;
}
__device__ __forceinline__ uint4 ld_ef(const void* gp, uint64_t pol) {
    uint4 v;
    asm volatile("ld.global.nc.L2::cache_hint.v4.u32 {%0,%1,%2,%3}, [%4], %5;"
                 : "=r"(v.x), "=r"(v.y), "=r"(v.z), "=r"(v.w)
                 : "l"(gp), "l"(pol));
    return v;
}
__device__ __forceinline__ void st_ef(void* gp, uint4 v, uint64_t pol) {
    asm volatile("st.global.L2::cache_hint.v4.b32 [%0], {%1,%2,%3,%4}, %5;"
                 :: "l"(gp), "r"(v.x), "r"(v.y), "r"(v.z), "r"(v.w), "l"(pol)
                 : "memory");
}

// ---- launch 0: B' build [32][1024] + permuted bias --------------------------
// col j = q*256 + o*8 + hl ; h = q*8+hl ; o = (j>>3)&31
__global__ void preB_kernel(const float* __restrict__ ew2,
                            const float* __restrict__ eb2) {
    int b = blockIdx.x, tid = threadIdx.x;
    if (b < 128) {
        int i = b * 256 + tid;
        int k = i >> 10, j = i & 1023;
        int h = ((j >> 8) << 3) + (j & 7), o = (j >> 3) & 31;
        g_Bt[i] = __float2half(ew2[k * 1024 + h * 32 + o]);
    } else {
#pragma unroll
        for (int u = 0; u < 4; u++) {
            int j = tid * 4 + u;
            int h = ((j >> 8) << 3) + (j & 7), o = (j >> 3) & 31;
            g_biasp[j] = eb2[h * 32 + o];
        }
    }
}

// ---- launch 1: t = relu(rel@ew1+eb1) -> fp16 --------------------------------
__global__ void preT_kernel(const float4* __restrict__ rel4,
                            const float* __restrict__ ew1,
                            const float* __restrict__ eb1) {
    int g = blockIdx.x * 256 + threadIdx.x;
    int e = g >> 5, k = g & 31;
    float4 r = rel4[e];
    float v = eb1[k] + r.x * ew1[k] + r.y * ew1[32 + k] + r.z * ew1[64 + k] +
              r.w * ew1[96 + k];
    g_tA[(size_t)e * 32 + k] = __float2half(fmaxf(v, 0.f));
}

// ---- launch 2: h0 projection + zero g_agg -----------------------------------
__global__ __launch_bounds__(256) void h0z_kernel(const float* __restrict__ x,
                                                  const float* __restrict__ pw1,
                                                  const float* __restrict__ pb1,
                                                  const float* __restrict__ pw2,
                                                  const float* __restrict__ pb2) {
    __shared__ float sW1[1024], sW2[1024];
    int tid = threadIdx.x, lane = tid & 31;
    g_agg[blockIdx.x * 256 + tid] = 0.f;
    for (int i = tid; i < 1024; i += 256) { sW1[i] = pw1[i]; sW2[i] = pw2[i]; }
    __syncthreads();
    int gw = blockIdx.x * 8 + (tid >> 5);
    float xr = x[(size_t)gw * 32 + lane];
    float t1 = pb1[lane];
#pragma unroll
    for (int h = 0; h < 32; h++)
        t1 = fmaf(__shfl_sync(0xffffffffu, xr, h), sW1[h * 32 + lane], t1);
    t1 = fmaxf(t1, 0.f);
    float o = pb2[lane];
#pragma unroll
    for (int h = 0; h < 32; h++)
        o = fmaf(__shfl_sync(0xffffffffu, t1, h), sW2[h * 32 + lane], o);
    g_h[(size_t)gw * 32 + lane] = o;
}

// ---- launch 3 (PROFILED): We GEMM [128x32]@[32x1024] wmma -------------------
#define SA 0                 // 128*40*2  = 10240
#define SB 10240             // 32*1032*2 = 66048
#define SC 76288             // 8*16*68*4 = 34816
#define SBIAS 111104         // 4096
#define STOT 115200

__global__ __launch_bounds__(256, 2) void we_wmma_kernel() {
    extern __shared__ char sm[];
    __half* sA = (__half*)(sm + SA);
    __half* sB = (__half*)(sm + SB);
    float* sC = (float*)(sm + SC);
    float* sBias = (float*)(sm + SBIAS);
    int tid = threadIdx.x, wid = tid >> 5, lane = tid & 31;
    uint64_t pol = mkpol_ef();

    // A tile: 128 edges x 32 halves, pad stride 40
    const uint4* ga = (const uint4*)(g_tA + (size_t)blockIdx.x * 128 * 32);
#pragma unroll
    for (int r = 0; r < 2; r++) {
        int i = tid + r * 256, row = i >> 2, c = i & 3;
        *(uint4*)(sA + row * 40 + c * 8) = ga[i];
    }
    // B' full: 32 x 1024 halves, pad stride 1032
    const uint4* gb = (const uint4*)(const void*)g_Bt;
#pragma unroll
    for (int r = 0; r < 16; r++) {
        int i = tid + r * 256, row = i >> 7, c = i & 127;
        *(uint4*)(sB + row * 1032 + c * 8) = gb[i];
    }
#pragma unroll
    for (int r = 0; r < 4; r++) sBias[tid + r * 256] = g_biasp[tid + r * 256];
    __syncthreads();

    float* sCw = sC + wid * 16 * 68;
    const int rsub = lane >> 3, ch = lane & 7;
    for (int nt = 0; nt < 16; nt++) {
        wmma::fragment<wmma::accumulator, 16, 16, 16, float> acc[4];
#pragma unroll
        for (int f = 0; f < 4; f++) wmma::fill_fragment(acc[f], 0.f);
#pragma unroll
        for (int k = 0; k < 2; k++) {
            wmma::fragment<wmma::matrix_a, 16, 16, 16, __half, wmma::row_major> af;
            wmma::load_matrix_sync(af, sA + (wid * 16) * 40 + k * 16, 40);
#pragma unroll
            for (int f = 0; f < 4; f++) {
                wmma::fragment<wmma::matrix_b, 16, 16, 16, __half, wmma::row_major> bf;
                wmma::load_matrix_sync(bf, sB + (k * 16) * 1032 + nt * 64 + f * 16,
                                       1032);
                wmma::mma_sync(acc[f], af, bf, acc[f]);
            }
        }
        __syncwarp();
#pragma unroll
        for (int f = 0; f < 4; f++)
            wmma::store_matrix_sync(sCw + f * 16, acc[f], 68, wmma::mem_row_major);
        __syncwarp();
        const float* bp = sBias + nt * 64 + ch * 8;
#pragma unroll
        for (int p = 0; p < 4; p++) {
            int row = p * 4 + rsub;
            const float* rp = sCw + row * 68 + ch * 8;
            float4 v0 = *(const float4*)rp;
            float4 v1 = *(const float4*)(rp + 4);
            __half2 a = __floats2half2_rn(v0.x + bp[0], v0.y + bp[1]);
            __half2 b2 = __floats2half2_rn(v0.z + bp[2], v0.w + bp[3]);
            __half2 c2 = __floats2half2_rn(v1.x + bp[4], v1.y + bp[5]);
            __half2 d2 = __floats2half2_rn(v1.z + bp[6], v1.w + bp[7]);
            int e = blockIdx.x * 128 + wid * 16 + row;
            uint4 pk = make_uint4(*(uint32_t*)&a, *(uint32_t*)&b2,
                                  *(uint32_t*)&c2, *(uint32_t*)&d2);
            st_ef((char*)(void*)g_We + (size_t)e * 2048 + nt * 128 + ch * 16, pk,
                  pol);
        }
        __syncwarp();
    }
}

// ---- msg + scatter, 2 edges per warp (DRAM-bound, ~roofline) ----------------
__global__ __launch_bounds__(256) void msg_kernel(const int* __restrict__ src,
                                                  const int* __restrict__ dst) {
    __shared__ __align__(16) float ns[8][4][32];
    const int w = threadIdx.x >> 5, lane = threadIdx.x & 31;
    const int e0 = blockIdx.x * 16 + w * 2;
    uint64_t pol = mkpol_ef();
    int s0 = __ldg(&src[e0]), s1 = __ldg(&src[e0 + 1]);
    int d0 = __ldg(&dst[e0]), d1 = __ldg(&dst[e0 + 1]);
    ns[w][0][lane] = g_h[(size_t)s0 * 32 + lane];
    ns[w][1][lane] = g_h[N32 + (size_t)s0 * 32 + lane];
    ns[w][2][lane] = g_h[(size_t)s1 * 32 + lane];
    ns[w][3][lane] = g_h[N32 + (size_t)s1 * 32 + lane];
    uint4 q[8];
#pragma unroll
    for (int ee = 0; ee < 2; ee++)
#pragma unroll
        for (int qi = 0; qi < 4; qi++)
            q[ee * 4 + qi] = ld_ef((const char*)(const void*)g_We +
                                       (size_t)(e0 + ee) * 2048 + qi * 512 +
                                       lane * 16,
                                   pol);
    __syncwarp();
    float acc[4] = {0.f, 0.f, 0.f, 0.f};
#pragma unroll
    for (int ee = 0; ee < 2; ee++) {
#pragma unroll
        for (int qi = 0; qi < 4; qi++) {
            uint32_t w4[4] = {q[ee * 4 + qi].x, q[ee * 4 + qi].y,
                              q[ee * 4 + qi].z, q[ee * 4 + qi].w};
#pragma unroll
            for (int u = 0; u < 4; u++) {
                float2 wf = __half22float2(*(__half2*)&w4[u]);
                int h = qi * 8 + 2 * u;
                float2 p0 = *(const float2*)&ns[w][ee * 2][h];
                float2 p1 = *(const float2*)&ns[w][ee * 2 + 1][h];
                acc[ee * 2] += p0.x * wf.x + p0.y * wf.y;
                acc[ee * 2 + 1] += p1.x * wf.x + p1.y * wf.y;
            }
        }
    }
#pragma unroll
    for (int ee = 0; ee < 2; ee++) {
        int d = ee ? d1 : d0;
        float a0 = acc[ee * 2], a1 = acc[ee * 2 + 1];
        float u = __shfl_down_sync(0xffffffffu, a0, 1);
        float v = __shfl_up_sync(0xffffffffu, a1, 1);
        if (!(lane & 1))
            asm volatile("red.global.add.v2.f32 [%0], {%1,%2};"
                         :: "l"(&g_agg[(size_t)d * 32 + lane]), "f"(a0), "f"(u)
                         : "memory");
        else
            asm volatile("red.global.add.v2.f32 [%0], {%1,%2};"
                         :: "l"(&g_agg[N32 + (size_t)d * 32 + lane - 1]), "f"(v),
                            "f"(a1)
                         : "memory");
    }
}

// ---- relu + GRU (warp per node), resets agg; padded smem (no conflicts) -----
__global__ __launch_bounds__(256) void gru_kernel(const float* __restrict__ convb,
                                                  const float* __restrict__ wih,
                                                  const float* __restrict__ whh,
                                                  const float* __restrict__ bih,
                                                  const float* __restrict__ bhh,
                                                  float* __restrict__ outp) {
    __shared__ float sWih[3104], sWhh[3104];  // [h][j] stride 97
    int tid = threadIdx.x, lane = tid & 31;
    for (int i = tid; i < 3072; i += 256) {
        int j = i >> 5, h = i & 31;
        sWih[h * 97 + j] = wih[i];
        sWhh[h * 97 + j] = whh[i];
    }
    __syncthreads();
    int gw = blockIdx.x * 8 + (tid >> 5);
    size_t idx = (size_t)gw * 32 + lane;
    float node = fmaxf(g_agg[idx] + convb[lane], 0.f);
    g_agg[idx] = 0.f;
    float hid = g_h[idx];
    float gx0 = bih[lane], gx1 = bih[32 + lane], gx2 = bih[64 + lane];
    float gh0 = bhh[lane], gh1 = bhh[32 + lane], gh2 = bhh[64 + lane];
#pragma unroll
    for (int h = 0; h < 32; h++) {
        float nv = __shfl_sync(0xffffffffu, node, h);
        float hv = __shfl_sync(0xffffffffu, hid, h);
        const float* wi = &sWih[h * 97];
        const float* wh = &sWhh[h * 97];
        gx0 = fmaf(nv, wi[lane], gx0);
        gx1 = fmaf(nv, wi[32 + lane], gx1);
        gx2 = fmaf(nv, wi[64 + lane], gx2);
        gh0 = fmaf(hv, wh[lane], gh0);
        gh1 = fmaf(hv, wh[32 + lane], gh1);
        gh2 = fmaf(hv, wh[64 + lane], gh2);
    }
    float r = fsig(gx0 + gh0);
    float z = fsig(gx1 + gh1);
    float n = tanhf(gx2 + r * gh2);
    float hn = (1.f - z) * n + z * hid;
    g_h[idx] = hn;
    if (outp) outp[idx] = hn;
}

// ------------------------- launch -------------------------------------------
extern "C" void kernel_launch(void* const* d_in, const int* in_sizes, int n_in,
                              void* d_out, int out_size) {
    const float* x     = (const float*)d_in[0];
    const float* rel   = (const float*)d_in[1];
    const float* pw1   = (const float*)d_in[2];
    const float* pb1   = (const float*)d_in[3];
    const float* pw2   = (const float*)d_in[4];
    const float* pb2   = (const float*)d_in[5];
    const float* ew1   = (const float*)d_in[6];
    const float* eb1   = (const float*)d_in[7];
    const float* ew2   = (const float*)d_in[8];
    const float* eb2   = (const float*)d_in[9];
    const float* convb = (const float*)d_in[10];
    const float* wih   = (const float*)d_in[11];
    const float* whh   = (const float*)d_in[12];
    const float* bih   = (const float*)d_in[13];
    const float* bhh   = (const float*)d_in[14];
    const int*   src   = (const int*)d_in[15];
    const int*   dst   = (const int*)d_in[16];
    float* out = (float*)d_out;

    cudaFuncSetAttribute(we_wmma_kernel,
                         cudaFuncAttributeMaxDynamicSharedMemorySize, STOT);
    preB_kernel<<<129, 256>>>(ew2, eb2);
    preT_kernel<<<(NEDGES * 32) / 256, 256>>>((const float4*)rel, ew1, eb1);
    h0z_kernel<<<(2 * NNODES) / 8, 256>>>(x, pw1, pb1, pw2, pb2);
    we_wmma_kernel<<<NEDGES / 128, 256, STOT>>>();
    for (int step = 0; step < 3; step++) {
        msg_kernel<<<NEDGES / 16, 256>>>(src, dst);
        gru_kernel<<<(2 * NNODES) / 8, 256>>>(convb, wih, whh, bih, bhh,
                                              step == 2 ? out : nullptr);
    }
}